// round 5
// baseline (speedup 1.0000x reference)
#include <cuda_runtime.h>
#include <math.h>
#include <float.h>

#define D_    1024
#define H_    16
#define HK_   8
#define HD_   64
#define FF_   3072
#define S_    1024
#define B_    4
#define TOK_  4096   // B*S
#define L_    4
#define WIN_  12

// ---------------- scratch (no allocations allowed) ----------------
__device__ float g_h   [TOK_ * D_];
__device__ float g_n   [TOK_ * D_];
__device__ float g_q   [TOK_ * H_  * HD_];
__device__ float g_k   [TOK_ * HK_ * HD_];
__device__ float g_v   [TOK_ * HK_ * HD_];
__device__ float g_att [TOK_ * H_  * HD_];
__device__ float g_gate[TOK_ * FF_];
__device__ float g_up  [TOK_ * FF_];
// tf32-prerounded weights
__device__ float g_wq[L_ * D_ * H_ * HD_];
__device__ float g_wk[L_ * D_ * HK_ * HD_];
__device__ float g_wv[L_ * D_ * HK_ * HD_];
__device__ float g_wo[L_ * H_ * HD_ * D_];
__device__ float g_wg[L_ * D_ * FF_];
__device__ float g_wu[L_ * D_ * FF_];
__device__ float g_wd[L_ * FF_ * D_];

// ---------------- helpers ----------------
__device__ __forceinline__ unsigned f2tf(float x) {
    unsigned r;
    asm("cvt.rna.tf32.f32 %0, %1;" : "=r"(r) : "f"(x));
    return r;
}
__device__ __forceinline__ float tfr(float x) { return __uint_as_float(f2tf(x)); }
__device__ __forceinline__ void cpasync16(float* dst_smem, const float* src_gmem) {
    unsigned d = (unsigned)__cvta_generic_to_shared(dst_smem);
    asm volatile("cp.async.cg.shared.global [%0], [%1], 16;"
                 :: "r"(d), "l"(src_gmem));
}
#define CP_COMMIT() asm volatile("cp.async.commit_group;")
#define CP_WAIT0()  asm volatile("cp.async.wait_group 0;")

// ---------------- tf32 pre-round (weights) ----------------
__global__ void tf32_round_kernel(const float* __restrict__ src,
                                  float* __restrict__ dst, int n4) {
    int i = blockIdx.x * blockDim.x + threadIdx.x;
    if (i < n4) {
        float4 v = *(const float4*)(src + i * 4);
        v.x = tfr(v.x); v.y = tfr(v.y); v.z = tfr(v.z); v.w = tfr(v.w);
        *(float4*)(dst + i * 4) = v;
    }
}

// ---------------- rmsnorm over 1024 cols, 1 block per row ----------------
// rnd != 0: emit tf32-rounded output (feeds GEMMs)
__global__ void rmsnorm_kernel(const float* __restrict__ x,
                               const float* __restrict__ w,
                               float* __restrict__ out, int rnd) {
    int row = blockIdx.x;
    const float* xr = x + (size_t)row * D_;
    int t = threadIdx.x;               // 256 threads, 4 floats each
    float4 v = *(const float4*)(xr + t * 4);
    float ss = v.x * v.x + v.y * v.y + v.z * v.z + v.w * v.w;
    #pragma unroll
    for (int o = 16; o; o >>= 1) ss += __shfl_xor_sync(0xffffffffu, ss, o);
    __shared__ float sh[8];
    if ((t & 31) == 0) sh[t >> 5] = ss;
    __syncthreads();
    float tot = 0.f;
    #pragma unroll
    for (int i = 0; i < 8; i++) tot += sh[i];
    float scale = rsqrtf(tot * (1.0f / D_) + 1e-6f);
    float4 wv = *(const float4*)(w + t * 4);
    float4 o4;
    o4.x = v.x * scale * wv.x;
    o4.y = v.y * scale * wv.y;
    o4.z = v.z * scale * wv.z;
    o4.w = v.w * scale * wv.w;
    if (rnd) { o4.x = tfr(o4.x); o4.y = tfr(o4.y); o4.z = tfr(o4.z); o4.w = tfr(o4.w); }
    *(float4*)(out + (size_t)row * D_ + t * 4) = o4;
}

// ---------------- TF32 tensor-core GEMM core (cp.async, warp tile 64x64) ----------------
// Block tile 128x128, BK=16, 128 threads (4 warps, 2x2). All inputs pre-rounded
// to tf32 so fragments are fed raw (no CVT in loop).
#define AST_ 20
#define BST_ 136
template <bool ACC>
__device__ __forceinline__ void gemm_core(const float* __restrict__ A,
                                          const float* __restrict__ B,
                                          float* __restrict__ C,
                                          int N, int K, int bx, int by) {
    __shared__ float As[2][128 * AST_];
    __shared__ float Bs[2][16 * BST_];

    int tid = threadIdx.x;
    int lane = tid & 31, wid = tid >> 5;
    int wr = wid >> 1;          // 0..1 (64-row slab)
    int wc = wid & 1;           // 0..1 (64-col slab)
    int tg = lane & 3;          // k index within fragment
    int grp = lane >> 2;        // m/n index within fragment

    const float* Ag = A + (size_t)(by * 128) * K;
    const float* Bg = B + bx * 128;

    int brow = tid >> 3;              // 0..15
    int bcol = (tid & 7) * 16;        // 0..112

    float acc[4][8][4];
    #pragma unroll
    for (int i = 0; i < 4; i++)
        #pragma unroll
        for (int j = 0; j < 8; j++)
            #pragma unroll
            for (int c = 0; c < 4; c++) acc[i][j][c] = 0.f;

    // prologue: stage 0 (thread tid copies A row tid; B row brow cols bcol..+15)
    {
        const float* ag = Ag + (size_t)tid * K;
        #pragma unroll
        for (int j = 0; j < 4; j++)
            cpasync16(&As[0][tid * AST_ + j * 4], ag + j * 4);
        const float* bg = Bg + (size_t)brow * N + bcol;
        #pragma unroll
        for (int j = 0; j < 4; j++)
            cpasync16(&Bs[0][brow * BST_ + bcol + j * 4], bg + j * 4);
        CP_COMMIT();
    }

    int nIter = K >> 4;
    for (int it = 0; it < nIter; it++) {
        int cur = it & 1;
        CP_WAIT0();
        __syncthreads();
        if (it + 1 < nIter) {
            int nxt = cur ^ 1;
            int k0n = (it + 1) << 4;
            const float* ag = Ag + (size_t)tid * K + k0n;
            #pragma unroll
            for (int j = 0; j < 4; j++)
                cpasync16(&As[nxt][tid * AST_ + j * 4], ag + j * 4);
            const float* bg = Bg + (size_t)(k0n + brow) * N + bcol;
            #pragma unroll
            for (int j = 0; j < 4; j++)
                cpasync16(&Bs[nxt][brow * BST_ + bcol + j * 4], bg + j * 4);
            CP_COMMIT();
        }

        #pragma unroll
        for (int kk = 0; kk < 16; kk += 8) {
            unsigned afr[4][4], bfr[8][2];
            #pragma unroll
            for (int mt = 0; mt < 4; mt++) {
                int m = wr * 64 + mt * 16 + grp;
                afr[mt][0] = __float_as_uint(As[cur][m * AST_ + kk + tg]);
                afr[mt][1] = __float_as_uint(As[cur][(m + 8) * AST_ + kk + tg]);
                afr[mt][2] = __float_as_uint(As[cur][m * AST_ + kk + tg + 4]);
                afr[mt][3] = __float_as_uint(As[cur][(m + 8) * AST_ + kk + tg + 4]);
            }
            #pragma unroll
            for (int nt = 0; nt < 8; nt++) {
                int n = wc * 64 + nt * 8 + grp;
                bfr[nt][0] = __float_as_uint(Bs[cur][(kk + tg) * BST_ + n]);
                bfr[nt][1] = __float_as_uint(Bs[cur][(kk + tg + 4) * BST_ + n]);
            }
            #pragma unroll
            for (int mt = 0; mt < 4; mt++)
                #pragma unroll
                for (int nt = 0; nt < 8; nt++) {
                    asm volatile(
                        "mma.sync.aligned.m16n8k8.row.col.f32.tf32.tf32.f32 "
                        "{%0,%1,%2,%3}, {%4,%5,%6,%7}, {%8,%9}, {%0,%1,%2,%3};"
                        : "+f"(acc[mt][nt][0]), "+f"(acc[mt][nt][1]),
                          "+f"(acc[mt][nt][2]), "+f"(acc[mt][nt][3])
                        : "r"(afr[mt][0]), "r"(afr[mt][1]),
                          "r"(afr[mt][2]), "r"(afr[mt][3]),
                          "r"(bfr[nt][0]), "r"(bfr[nt][1]));
                }
        }
        __syncthreads();
    }

    #pragma unroll
    for (int mt = 0; mt < 4; mt++) {
        int row0 = by * 128 + wr * 64 + mt * 16 + grp;
        #pragma unroll
        for (int nt = 0; nt < 8; nt++) {
            int col = bx * 128 + wc * 64 + nt * 8 + tg * 2;
            float* p0 = C + (size_t)row0 * N + col;
            float* p1 = C + (size_t)(row0 + 8) * N + col;
            if (ACC) {
                float2 cc0 = *(float2*)p0, cc1 = *(float2*)p1;
                cc0.x += acc[mt][nt][0]; cc0.y += acc[mt][nt][1];
                cc1.x += acc[mt][nt][2]; cc1.y += acc[mt][nt][3];
                *(float2*)p0 = cc0; *(float2*)p1 = cc1;
            } else {
                *(float2*)p0 = make_float2(acc[mt][nt][0], acc[mt][nt][1]);
                *(float2*)p1 = make_float2(acc[mt][nt][2], acc[mt][nt][3]);
            }
        }
    }
}

template <bool ACC>
__global__ void __launch_bounds__(128, 2)
gemm_tf32(const float* __restrict__ A, const float* __restrict__ B,
          float* __restrict__ C, int N, int K) {
    gemm_core<ACC>(A, B, C, N, K, blockIdx.x, blockIdx.y);
}

// fused QKV: bx 0..7 -> q (N=1024), 8..11 -> k (N=512), 12..15 -> v (N=512)
__global__ void __launch_bounds__(128, 2)
gemm_qkv(const float* __restrict__ A,
         const float* __restrict__ Wq, const float* __restrict__ Wk,
         const float* __restrict__ Wv,
         float* __restrict__ q, float* __restrict__ k, float* __restrict__ v) {
    int bx = blockIdx.x;
    if (bx < 8)       gemm_core<false>(A, Wq, q, 1024, D_, bx,      blockIdx.y);
    else if (bx < 12) gemm_core<false>(A, Wk, k,  512, D_, bx - 8,  blockIdx.y);
    else              gemm_core<false>(A, Wv, v,  512, D_, bx - 12, blockIdx.y);
}

// fused gate+up: bx 0..23 -> gate, 24..47 -> up (both N=3072)
__global__ void __launch_bounds__(128, 2)
gemm_gateup(const float* __restrict__ A,
            const float* __restrict__ Wg, const float* __restrict__ Wu,
            float* __restrict__ gate, float* __restrict__ up) {
    int bx = blockIdx.x;
    if (bx < 24) gemm_core<false>(A, Wg, gate, FF_, D_, bx,      blockIdx.y);
    else         gemm_core<false>(A, Wu, up,   FF_, D_, bx - 24, blockIdx.y);
}

// ---------------- per-head rmsnorm + RoPE (one warp per (token, head)) ----------------
#define LOG2_THETA 19.9315685693241741f
__global__ void qknorm_rope_kernel(float* __restrict__ x,
                                   const float* __restrict__ w, int nh) {
    int warp = (blockIdx.x * blockDim.x + threadIdx.x) >> 5;
    int lane = threadIdx.x & 31;
    int token = warp / nh;
    int s = token & (S_ - 1);          // position within sequence
    float* p = x + (size_t)warp * HD_;
    float a = p[lane], b = p[lane + 32];
    float ss = a * a + b * b;
    #pragma unroll
    for (int o = 16; o; o >>= 1) ss += __shfl_xor_sync(0xffffffffu, ss, o);
    float scale = rsqrtf(ss * (1.0f / HD_) + 1e-6f);
    a *= scale * w[lane];
    b *= scale * w[lane + 32];
    float inv = exp2f(-(float)lane * (LOG2_THETA / 32.0f));
    float ang = (float)s * inv;
    float c = cosf(ang), sn = sinf(ang);
    p[lane]      = a * c - b * sn;
    p[lane + 32] = b * c + a * sn;
}

// ---------------- flash attention: block = (b, h, 64 q rows), K-tile 32 ----------------
__global__ void __launch_bounds__(256)
attn_kernel(const float* __restrict__ q, const float* __restrict__ k,
            const float* __restrict__ v, const int* __restrict__ amask,
            float* __restrict__ out, int win) {
    __shared__ float Qs[64][65];
    __shared__ float Ks[32][65];
    __shared__ float Vs[32][64];
    __shared__ float Ps[64][33];

    int b = blockIdx.z, h = blockIdx.y;
    int q0 = blockIdx.x * 64;
    int kh = h >> 1;                       // GQA: 2 q-heads per kv-head
    int tid = threadIdx.x;
    int tx = tid & 7;
    int tyg = tid >> 3;
    int r0 = tyg * 2, r1 = r0 + 1;
    int d0 = tx * 8;

    for (int i = tid; i < 64 * 16; i += 256) {
        int r = i >> 4, c4 = (i & 15) << 2;
        float4 f = *(const float4*)(q + ((size_t)(b * S_ + q0 + r) * (H_ * HD_)) + h * HD_ + c4);
        Qs[r][c4] = f.x; Qs[r][c4 + 1] = f.y; Qs[r][c4 + 2] = f.z; Qs[r][c4 + 3] = f.w;
    }

    float m0 = -1e30f, m1 = -1e30f, l0 = 0.f, l1 = 0.f;
    float o0[8], o1[8];
    #pragma unroll
    for (int j = 0; j < 8; j++) { o0[j] = 0.f; o1[j] = 0.f; }

    int kt_lo = 0, kt_hi = (S_ / 32) - 1;
    if (win >= 0) {
        int lo = q0 - win; if (lo < 0) lo = 0;
        int hi = q0 + 63 + win; if (hi > S_ - 1) hi = S_ - 1;
        kt_lo = lo >> 5; kt_hi = hi >> 5;
    }
    const float scale = 0.125f;

    __syncthreads();
    for (int kt = kt_lo; kt <= kt_hi; kt++) {
        int kbase = b * S_ + kt * 32;
        for (int i = tid; i < 32 * 16; i += 256) {
            int r = i >> 4, c4 = (i & 15) << 2;
            size_t off = (size_t)(kbase + r) * (HK_ * HD_) + kh * HD_ + c4;
            float4 fk = *(const float4*)(k + off);
            float4 fv = *(const float4*)(v + off);
            Ks[r][c4] = fk.x; Ks[r][c4 + 1] = fk.y; Ks[r][c4 + 2] = fk.z; Ks[r][c4 + 3] = fk.w;
            *(float4*)&Vs[r][c4] = fv;
        }
        __syncthreads();

        float s0[4], s1[4];
        #pragma unroll
        for (int j = 0; j < 4; j++) { s0[j] = 0.f; s1[j] = 0.f; }
        #pragma unroll 8
        for (int d = 0; d < 64; d++) {
            float qa = Qs[r0][d], qb = Qs[r1][d];
            #pragma unroll
            for (int j = 0; j < 4; j++) {
                float kv = Ks[tx * 4 + j][d];
                s0[j] = fmaf(qa, kv, s0[j]);
                s1[j] = fmaf(qb, kv, s1[j]);
            }
        }
        #pragma unroll
        for (int j = 0; j < 4; j++) {
            int kpos = kt * 32 + tx * 4 + j;
            bool ok = (amask[b * S_ + kpos] != 0);
            float sa = s0[j] * scale, sb = s1[j] * scale;
            if (win >= 0) {
                int qa_ = q0 + r0, qb_ = q0 + r1;
                if (abs(qa_ - kpos) > win) sa = -1e30f;
                if (abs(qb_ - kpos) > win) sb = -1e30f;
            }
            if (!ok) { sa = -1e30f; sb = -1e30f; }
            s0[j] = sa; s1[j] = sb;
        }
        {
            float tm = fmaxf(fmaxf(s0[0], s0[1]), fmaxf(s0[2], s0[3]));
            #pragma unroll
            for (int o = 4; o; o >>= 1) tm = fmaxf(tm, __shfl_xor_sync(0xffffffffu, tm, o));
            float nm = fmaxf(m0, tm);
            float alpha = expf(m0 - nm);
            float ps = 0.f;
            #pragma unroll
            for (int j = 0; j < 4; j++) {
                float p = expf(s0[j] - nm);
                Ps[r0][tx * 4 + j] = p;
                ps += p;
            }
            #pragma unroll
            for (int o = 4; o; o >>= 1) ps += __shfl_xor_sync(0xffffffffu, ps, o);
            l0 = l0 * alpha + ps; m0 = nm;
            #pragma unroll
            for (int j = 0; j < 8; j++) o0[j] *= alpha;
        }
        {
            float tm = fmaxf(fmaxf(s1[0], s1[1]), fmaxf(s1[2], s1[3]));
            #pragma unroll
            for (int o = 4; o; o >>= 1) tm = fmaxf(tm, __shfl_xor_sync(0xffffffffu, tm, o));
            float nm = fmaxf(m1, tm);
            float alpha = expf(m1 - nm);
            float ps = 0.f;
            #pragma unroll
            for (int j = 0; j < 4; j++) {
                float p = expf(s1[j] - nm);
                Ps[r1][tx * 4 + j] = p;
                ps += p;
            }
            #pragma unroll
            for (int o = 4; o; o >>= 1) ps += __shfl_xor_sync(0xffffffffu, ps, o);
            l1 = l1 * alpha + ps; m1 = nm;
            #pragma unroll
            for (int j = 0; j < 8; j++) o1[j] *= alpha;
        }
        __syncthreads();
        #pragma unroll 4
        for (int kk = 0; kk < 32; kk++) {
            float p0 = Ps[r0][kk], p1 = Ps[r1][kk];
            #pragma unroll
            for (int j = 0; j < 8; j++) {
                float vv = Vs[kk][d0 + j];
                o0[j] = fmaf(p0, vv, o0[j]);
                o1[j] = fmaf(p1, vv, o1[j]);
            }
        }
        __syncthreads();
    }

    float il0 = 1.0f / l0, il1 = 1.0f / l1;
    size_t base0 = (size_t)(b * S_ + q0 + r0) * (H_ * HD_) + h * HD_ + d0;
    size_t base1 = (size_t)(b * S_ + q0 + r1) * (H_ * HD_) + h * HD_ + d0;
    #pragma unroll
    for (int j = 0; j < 8; j++) {
        out[base0 + j] = tfr(o0[j] * il0);   // pre-round for o-proj GEMM
        out[base1 + j] = tfr(o1[j] * il1);
    }
}

// ---------------- SwiGLU elementwise: gate = tf32(silu(gate) * up) ----------------
__global__ void silu_mul_kernel(float* __restrict__ gate,
                                const float* __restrict__ up, int n) {
    int i = blockIdx.x * blockDim.x + threadIdx.x;
    if (i < n) {
        float g = gate[i];
        float s = g / (1.0f + expf(-g));
        gate[i] = tfr(s * up[i]);           // pre-round for down GEMM
    }
}

// ---------------- host orchestration ----------------
extern "C" void kernel_launch(void* const* d_in, const int* in_sizes, int n_in,
                              void* d_out, int out_size) {
    const float* x      = (const float*)d_in[0];
    const float* wq     = (const float*)d_in[1];
    const float* wk     = (const float*)d_in[2];
    const float* wv     = (const float*)d_in[3];
    const float* wo     = (const float*)d_in[4];
    const float* qnw    = (const float*)d_in[5];
    const float* knw    = (const float*)d_in[6];
    const float* ln1    = (const float*)d_in[7];
    const float* ln2    = (const float*)d_in[8];
    const float* wg     = (const float*)d_in[9];
    const float* wu     = (const float*)d_in[10];
    const float* wd     = (const float*)d_in[11];
    const float* normw  = (const float*)d_in[12];
    const int*   amask  = (const int*)d_in[13];

    float *h, *n, *q, *k, *v, *att, *gate, *up;
    float *cwq, *cwk, *cwv, *cwo, *cwg, *cwu, *cwd;
    cudaGetSymbolAddress((void**)&h,    g_h);
    cudaGetSymbolAddress((void**)&n,    g_n);
    cudaGetSymbolAddress((void**)&q,    g_q);
    cudaGetSymbolAddress((void**)&k,    g_k);
    cudaGetSymbolAddress((void**)&v,    g_v);
    cudaGetSymbolAddress((void**)&att,  g_att);
    cudaGetSymbolAddress((void**)&gate, g_gate);
    cudaGetSymbolAddress((void**)&up,   g_up);
    cudaGetSymbolAddress((void**)&cwq,  g_wq);
    cudaGetSymbolAddress((void**)&cwk,  g_wk);
    cudaGetSymbolAddress((void**)&cwv,  g_wv);
    cudaGetSymbolAddress((void**)&cwo,  g_wo);
    cudaGetSymbolAddress((void**)&cwg,  g_wg);
    cudaGetSymbolAddress((void**)&cwu,  g_wu);
    cudaGetSymbolAddress((void**)&cwd,  g_wd);

    // pre-round all weights to tf32 (RNA) once per call
    {
        struct { const float* s; float* d; int n; } cv[7] = {
            { wq, cwq, L_ * D_ * H_ * HD_ },
            { wk, cwk, L_ * D_ * HK_ * HD_ },
            { wv, cwv, L_ * D_ * HK_ * HD_ },
            { wo, cwo, L_ * H_ * HD_ * D_ },
            { wg, cwg, L_ * D_ * FF_ },
            { wu, cwu, L_ * D_ * FF_ },
            { wd, cwd, L_ * FF_ * D_ },
        };
        for (int i = 0; i < 7; i++) {
            int n4 = cv[i].n / 4;
            tf32_round_kernel<<<(n4 + 255) / 256, 256>>>(cv[i].s, cv[i].d, n4);
        }
    }

    cudaMemcpyAsync(h, x, (size_t)TOK_ * D_ * sizeof(float),
                    cudaMemcpyDeviceToDevice, 0);

    dim3 gQKV (16, TOK_ / 128);              // 512 blocks
    dim3 gGU  (48, TOK_ / 128);              // 1536 blocks
    dim3 g1024(D_ / 128, TOK_ / 128);        // 256 blocks

    for (int l = 0; l < L_; l++) {
        const float* wq_l = cwq + (size_t)l * D_ * H_ * HD_;
        const float* wk_l = cwk + (size_t)l * D_ * HK_ * HD_;
        const float* wv_l = cwv + (size_t)l * D_ * HK_ * HD_;
        const float* wo_l = cwo + (size_t)l * H_ * HD_ * D_;
        const float* wg_l = cwg + (size_t)l * D_ * FF_;
        const float* wu_l = cwu + (size_t)l * D_ * FF_;
        const float* wd_l = cwd + (size_t)l * FF_ * D_;

        rmsnorm_kernel<<<TOK_, 256>>>(h, ln1 + l * D_, n, 1);

        gemm_qkv<<<gQKV, 128>>>(n, wq_l, wk_l, wv_l, q, k, v);

        qknorm_rope_kernel<<<(TOK_ * H_)  / 4, 128>>>(q, qnw + l * HD_, H_);
        qknorm_rope_kernel<<<(TOK_ * HK_) / 4, 128>>>(k, knw + l * HD_, HK_);

        attn_kernel<<<dim3(S_ / 64, H_, B_), 256>>>(
            q, k, v, amask, att, (l & 1) ? WIN_ : -1);

        gemm_tf32<true><<<g1024, 128>>>(att, wo_l, h, D_, H_ * HD_);

        rmsnorm_kernel<<<TOK_, 256>>>(h, ln2 + l * D_, n, 1);

        gemm_gateup<<<gGU, 128>>>(n, wg_l, wu_l, gate, up);

        int nel = TOK_ * FF_;
        silu_mul_kernel<<<(nel + 255) / 256, 256>>>(gate, up, nel);

        gemm_tf32<true><<<g1024, 128>>>(gate, wd_l, h, D_, FF_);
    }

    rmsnorm_kernel<<<TOK_, 256>>>(h, normw, (float*)d_out, 0);
}

// round 6
// speedup vs baseline: 1.1103x; 1.1103x over previous
#include <cuda_runtime.h>
#include <math.h>
#include <float.h>

#define D_    1024
#define H_    16
#define HK_   8
#define HD_   64
#define FF_   3072
#define S_    1024
#define B_    4
#define TOK_  4096   // B*S
#define L_    4
#define WIN_  12

// ---------------- scratch (no allocations allowed) ----------------
__device__ float g_h   [TOK_ * D_];
__device__ float g_n   [TOK_ * D_];
__device__ float g_q   [TOK_ * H_  * HD_];
__device__ float g_k   [TOK_ * HK_ * HD_];
__device__ float g_v   [TOK_ * HK_ * HD_];
__device__ float g_att [TOK_ * H_  * HD_];
__device__ float g_gate[TOK_ * FF_];
__device__ float g_up  [TOK_ * FF_];
// tf32-prerounded weights
__device__ float g_wq[L_ * D_ * H_ * HD_];
__device__ float g_wk[L_ * D_ * HK_ * HD_];
__device__ float g_wv[L_ * D_ * HK_ * HD_];
__device__ float g_wo[L_ * H_ * HD_ * D_];
__device__ float g_wg[L_ * D_ * FF_];
__device__ float g_wu[L_ * D_ * FF_];
__device__ float g_wd[L_ * FF_ * D_];

// ---------------- helpers ----------------
__device__ __forceinline__ unsigned f2tf(float x) {
    unsigned r;
    asm("cvt.rna.tf32.f32 %0, %1;" : "=r"(r) : "f"(x));
    return r;
}
__device__ __forceinline__ float tfr(float x) { return __uint_as_float(f2tf(x)); }
__device__ __forceinline__ void cpasync16(float* dst_smem, const float* src_gmem) {
    unsigned d = (unsigned)__cvta_generic_to_shared(dst_smem);
    asm volatile("cp.async.cg.shared.global [%0], [%1], 16;"
                 :: "r"(d), "l"(src_gmem));
}
#define CP_COMMIT() asm volatile("cp.async.commit_group;")
#define CP_WAIT0()  asm volatile("cp.async.wait_group 0;")

// ---------------- tf32 pre-round (weights) ----------------
__global__ void tf32_round_kernel(const float* __restrict__ src,
                                  float* __restrict__ dst, int n4) {
    int i = blockIdx.x * blockDim.x + threadIdx.x;
    if (i < n4) {
        float4 v = *(const float4*)(src + i * 4);
        v.x = tfr(v.x); v.y = tfr(v.y); v.z = tfr(v.z); v.w = tfr(v.w);
        *(float4*)(dst + i * 4) = v;
    }
}

// ---------------- rmsnorm over 1024 cols, 1 block per row ----------------
// rnd != 0: emit tf32-rounded output (feeds GEMMs)
__global__ void rmsnorm_kernel(const float* __restrict__ x,
                               const float* __restrict__ w,
                               float* __restrict__ out, int rnd) {
    int row = blockIdx.x;
    const float* xr = x + (size_t)row * D_;
    int t = threadIdx.x;               // 256 threads, 4 floats each
    float4 v = *(const float4*)(xr + t * 4);
    float ss = v.x * v.x + v.y * v.y + v.z * v.z + v.w * v.w;
    #pragma unroll
    for (int o = 16; o; o >>= 1) ss += __shfl_xor_sync(0xffffffffu, ss, o);
    __shared__ float sh[8];
    if ((t & 31) == 0) sh[t >> 5] = ss;
    __syncthreads();
    float tot = 0.f;
    #pragma unroll
    for (int i = 0; i < 8; i++) tot += sh[i];
    float scale = rsqrtf(tot * (1.0f / D_) + 1e-6f);
    float4 wv = *(const float4*)(w + t * 4);
    float4 o4;
    o4.x = v.x * scale * wv.x;
    o4.y = v.y * scale * wv.y;
    o4.z = v.z * scale * wv.z;
    o4.w = v.w * scale * wv.w;
    if (rnd) { o4.x = tfr(o4.x); o4.y = tfr(o4.y); o4.z = tfr(o4.z); o4.w = tfr(o4.w); }
    *(float4*)(out + (size_t)row * D_ + t * 4) = o4;
}

// ---------------- TF32 tensor-core GEMM core (cp.async, 8 warps, no in-loop CVT) ----------------
// Block tile 128x128, BK=16, 256 threads (8 warps, 2x4). Warp tile 64x32.
// All inputs pre-rounded to tf32; fragments fed raw from smem.
#define AST_ 20
#define BST_ 136
template <bool ACC>
__device__ __forceinline__ void gemm_core(const float* __restrict__ A,
                                          const float* __restrict__ B,
                                          float* __restrict__ C,
                                          int N, int K, int bx, int by) {
    __shared__ float As[2][128 * AST_];
    __shared__ float Bs[2][16 * BST_];

    int tid = threadIdx.x;
    int lane = tid & 31, wid = tid >> 5;
    int wr = wid >> 2;          // 0..1  (64-row slab)
    int wc = wid & 3;           // 0..3  (32-col slab)
    int tg = lane & 3;          // k index within fragment
    int grp = lane >> 2;        // m/n index within fragment

    const float* Ag = A + (size_t)(by * 128) * K;
    const float* Bg = B + bx * 128;

    // cp.async plan: 2 x 16B chunks per thread for each of A and B
    int c0 = tid * 2, c1 = tid * 2 + 1;
    int ar0 = c0 >> 2, ac0 = (c0 & 3) << 2;
    int ar1 = c1 >> 2, ac1 = (c1 & 3) << 2;
    int br0 = c0 >> 5, bc0 = (c0 & 31) << 2;
    int br1 = c1 >> 5, bc1 = (c1 & 31) << 2;

    float acc[4][4][4];
    #pragma unroll
    for (int i = 0; i < 4; i++)
        #pragma unroll
        for (int j = 0; j < 4; j++)
            #pragma unroll
            for (int c = 0; c < 4; c++) acc[i][j][c] = 0.f;

    // prologue: stage 0
    cpasync16(&As[0][ar0 * AST_ + ac0], Ag + (size_t)ar0 * K + ac0);
    cpasync16(&As[0][ar1 * AST_ + ac1], Ag + (size_t)ar1 * K + ac1);
    cpasync16(&Bs[0][br0 * BST_ + bc0], Bg + (size_t)br0 * N + bc0);
    cpasync16(&Bs[0][br1 * BST_ + bc1], Bg + (size_t)br1 * N + bc1);
    CP_COMMIT();

    int nIter = K >> 4;
    for (int it = 0; it < nIter; it++) {
        int cur = it & 1;
        CP_WAIT0();
        __syncthreads();
        if (it + 1 < nIter) {
            int nxt = cur ^ 1;
            int k0n = (it + 1) << 4;
            cpasync16(&As[nxt][ar0 * AST_ + ac0], Ag + (size_t)ar0 * K + k0n + ac0);
            cpasync16(&As[nxt][ar1 * AST_ + ac1], Ag + (size_t)ar1 * K + k0n + ac1);
            cpasync16(&Bs[nxt][br0 * BST_ + bc0], Bg + (size_t)(k0n + br0) * N + bc0);
            cpasync16(&Bs[nxt][br1 * BST_ + bc1], Bg + (size_t)(k0n + br1) * N + bc1);
            CP_COMMIT();
        }

        #pragma unroll
        for (int kk = 0; kk < 16; kk += 8) {
            unsigned afr[4][4], bfr[4][2];
            #pragma unroll
            for (int mt = 0; mt < 4; mt++) {
                int m = wr * 64 + mt * 16 + grp;
                afr[mt][0] = __float_as_uint(As[cur][m * AST_ + kk + tg]);
                afr[mt][1] = __float_as_uint(As[cur][(m + 8) * AST_ + kk + tg]);
                afr[mt][2] = __float_as_uint(As[cur][m * AST_ + kk + tg + 4]);
                afr[mt][3] = __float_as_uint(As[cur][(m + 8) * AST_ + kk + tg + 4]);
            }
            #pragma unroll
            for (int nt = 0; nt < 4; nt++) {
                int n = wc * 32 + nt * 8 + grp;
                bfr[nt][0] = __float_as_uint(Bs[cur][(kk + tg) * BST_ + n]);
                bfr[nt][1] = __float_as_uint(Bs[cur][(kk + tg + 4) * BST_ + n]);
            }
            #pragma unroll
            for (int mt = 0; mt < 4; mt++)
                #pragma unroll
                for (int nt = 0; nt < 4; nt++) {
                    asm volatile(
                        "mma.sync.aligned.m16n8k8.row.col.f32.tf32.tf32.f32 "
                        "{%0,%1,%2,%3}, {%4,%5,%6,%7}, {%8,%9}, {%0,%1,%2,%3};"
                        : "+f"(acc[mt][nt][0]), "+f"(acc[mt][nt][1]),
                          "+f"(acc[mt][nt][2]), "+f"(acc[mt][nt][3])
                        : "r"(afr[mt][0]), "r"(afr[mt][1]),
                          "r"(afr[mt][2]), "r"(afr[mt][3]),
                          "r"(bfr[nt][0]), "r"(bfr[nt][1]));
                }
        }
        __syncthreads();
    }

    #pragma unroll
    for (int mt = 0; mt < 4; mt++) {
        int row0 = by * 128 + wr * 64 + mt * 16 + grp;
        #pragma unroll
        for (int nt = 0; nt < 4; nt++) {
            int col = bx * 128 + wc * 32 + nt * 8 + tg * 2;
            float* p0 = C + (size_t)row0 * N + col;
            float* p1 = C + (size_t)(row0 + 8) * N + col;
            if (ACC) {
                float2 cc0 = *(float2*)p0, cc1 = *(float2*)p1;
                cc0.x += acc[mt][nt][0]; cc0.y += acc[mt][nt][1];
                cc1.x += acc[mt][nt][2]; cc1.y += acc[mt][nt][3];
                *(float2*)p0 = cc0; *(float2*)p1 = cc1;
            } else {
                *(float2*)p0 = make_float2(acc[mt][nt][0], acc[mt][nt][1]);
                *(float2*)p1 = make_float2(acc[mt][nt][2], acc[mt][nt][3]);
            }
        }
    }
}

template <bool ACC>
__global__ void __launch_bounds__(256, 2)
gemm_tf32(const float* __restrict__ A, const float* __restrict__ B,
          float* __restrict__ C, int N, int K) {
    gemm_core<ACC>(A, B, C, N, K, blockIdx.x, blockIdx.y);
}

// fused QKV: bx 0..7 -> q (N=1024), 8..11 -> k (N=512), 12..15 -> v (N=512)
__global__ void __launch_bounds__(256, 2)
gemm_qkv(const float* __restrict__ A,
         const float* __restrict__ Wq, const float* __restrict__ Wk,
         const float* __restrict__ Wv,
         float* __restrict__ q, float* __restrict__ k, float* __restrict__ v) {
    int bx = blockIdx.x;
    if (bx < 8)       gemm_core<false>(A, Wq, q, 1024, D_, bx,      blockIdx.y);
    else if (bx < 12) gemm_core<false>(A, Wk, k,  512, D_, bx - 8,  blockIdx.y);
    else              gemm_core<false>(A, Wv, v,  512, D_, bx - 12, blockIdx.y);
}

// fused gate+up: bx 0..23 -> gate, 24..47 -> up (both N=3072)
__global__ void __launch_bounds__(256, 2)
gemm_gateup(const float* __restrict__ A,
            const float* __restrict__ Wg, const float* __restrict__ Wu,
            float* __restrict__ gate, float* __restrict__ up) {
    int bx = blockIdx.x;
    if (bx < 24) gemm_core<false>(A, Wg, gate, FF_, D_, bx,      blockIdx.y);
    else         gemm_core<false>(A, Wu, up,   FF_, D_, bx - 24, blockIdx.y);
}

// ---------------- per-head rmsnorm + RoPE (one warp per (token, head)) ----------------
#define LOG2_THETA 19.9315685693241741f
__global__ void qknorm_rope_kernel(float* __restrict__ x,
                                   const float* __restrict__ w, int nh) {
    int warp = (blockIdx.x * blockDim.x + threadIdx.x) >> 5;
    int lane = threadIdx.x & 31;
    int token = warp / nh;
    int s = token & (S_ - 1);          // position within sequence
    float* p = x + (size_t)warp * HD_;
    float a = p[lane], b = p[lane + 32];
    float ss = a * a + b * b;
    #pragma unroll
    for (int o = 16; o; o >>= 1) ss += __shfl_xor_sync(0xffffffffu, ss, o);
    float scale = rsqrtf(ss * (1.0f / HD_) + 1e-6f);
    a *= scale * w[lane];
    b *= scale * w[lane + 32];
    float inv = exp2f(-(float)lane * (LOG2_THETA / 32.0f));
    float ang = (float)s * inv;
    float c = cosf(ang), sn = sinf(ang);
    p[lane]      = a * c - b * sn;
    p[lane + 32] = b * c + a * sn;
}

// ---------------- flash attention: block = (b, h, 64 q rows), K-tile 32 ----------------
__global__ void __launch_bounds__(256)
attn_kernel(const float* __restrict__ q, const float* __restrict__ k,
            const float* __restrict__ v, const int* __restrict__ amask,
            float* __restrict__ out, int win) {
    __shared__ float Qs[64][65];
    __shared__ float Ks[32][65];
    __shared__ float Vs[32][64];
    __shared__ float Ps[64][33];

    int b = blockIdx.z, h = blockIdx.y;
    int q0 = blockIdx.x * 64;
    int kh = h >> 1;                       // GQA: 2 q-heads per kv-head
    int tid = threadIdx.x;
    int tx = tid & 7;
    int tyg = tid >> 3;
    int r0 = tyg * 2, r1 = r0 + 1;
    int d0 = tx * 8;

    for (int i = tid; i < 64 * 16; i += 256) {
        int r = i >> 4, c4 = (i & 15) << 2;
        float4 f = *(const float4*)(q + ((size_t)(b * S_ + q0 + r) * (H_ * HD_)) + h * HD_ + c4);
        Qs[r][c4] = f.x; Qs[r][c4 + 1] = f.y; Qs[r][c4 + 2] = f.z; Qs[r][c4 + 3] = f.w;
    }

    float m0 = -1e30f, m1 = -1e30f, l0 = 0.f, l1 = 0.f;
    float o0[8], o1[8];
    #pragma unroll
    for (int j = 0; j < 8; j++) { o0[j] = 0.f; o1[j] = 0.f; }

    int kt_lo = 0, kt_hi = (S_ / 32) - 1;
    if (win >= 0) {
        int lo = q0 - win; if (lo < 0) lo = 0;
        int hi = q0 + 63 + win; if (hi > S_ - 1) hi = S_ - 1;
        kt_lo = lo >> 5; kt_hi = hi >> 5;
    }
    const float scale = 0.125f;

    __syncthreads();
    for (int kt = kt_lo; kt <= kt_hi; kt++) {
        int kbase = b * S_ + kt * 32;
        for (int i = tid; i < 32 * 16; i += 256) {
            int r = i >> 4, c4 = (i & 15) << 2;
            size_t off = (size_t)(kbase + r) * (HK_ * HD_) + kh * HD_ + c4;
            float4 fk = *(const float4*)(k + off);
            float4 fv = *(const float4*)(v + off);
            Ks[r][c4] = fk.x; Ks[r][c4 + 1] = fk.y; Ks[r][c4 + 2] = fk.z; Ks[r][c4 + 3] = fk.w;
            *(float4*)&Vs[r][c4] = fv;
        }
        __syncthreads();

        float s0[4], s1[4];
        #pragma unroll
        for (int j = 0; j < 4; j++) { s0[j] = 0.f; s1[j] = 0.f; }
        #pragma unroll 8
        for (int d = 0; d < 64; d++) {
            float qa = Qs[r0][d], qb = Qs[r1][d];
            #pragma unroll
            for (int j = 0; j < 4; j++) {
                float kv = Ks[tx * 4 + j][d];
                s0[j] = fmaf(qa, kv, s0[j]);
                s1[j] = fmaf(qb, kv, s1[j]);
            }
        }
        #pragma unroll
        for (int j = 0; j < 4; j++) {
            int kpos = kt * 32 + tx * 4 + j;
            bool ok = (amask[b * S_ + kpos] != 0);
            float sa = s0[j] * scale, sb = s1[j] * scale;
            if (win >= 0) {
                int qa_ = q0 + r0, qb_ = q0 + r1;
                if (abs(qa_ - kpos) > win) sa = -1e30f;
                if (abs(qb_ - kpos) > win) sb = -1e30f;
            }
            if (!ok) { sa = -1e30f; sb = -1e30f; }
            s0[j] = sa; s1[j] = sb;
        }
        {
            float tm = fmaxf(fmaxf(s0[0], s0[1]), fmaxf(s0[2], s0[3]));
            #pragma unroll
            for (int o = 4; o; o >>= 1) tm = fmaxf(tm, __shfl_xor_sync(0xffffffffu, tm, o));
            float nm = fmaxf(m0, tm);
            float alpha = expf(m0 - nm);
            float ps = 0.f;
            #pragma unroll
            for (int j = 0; j < 4; j++) {
                float p = expf(s0[j] - nm);
                Ps[r0][tx * 4 + j] = p;
                ps += p;
            }
            #pragma unroll
            for (int o = 4; o; o >>= 1) ps += __shfl_xor_sync(0xffffffffu, ps, o);
            l0 = l0 * alpha + ps; m0 = nm;
            #pragma unroll
            for (int j = 0; j < 8; j++) o0[j] *= alpha;
        }
        {
            float tm = fmaxf(fmaxf(s1[0], s1[1]), fmaxf(s1[2], s1[3]));
            #pragma unroll
            for (int o = 4; o; o >>= 1) tm = fmaxf(tm, __shfl_xor_sync(0xffffffffu, tm, o));
            float nm = fmaxf(m1, tm);
            float alpha = expf(m1 - nm);
            float ps = 0.f;
            #pragma unroll
            for (int j = 0; j < 4; j++) {
                float p = expf(s1[j] - nm);
                Ps[r1][tx * 4 + j] = p;
                ps += p;
            }
            #pragma unroll
            for (int o = 4; o; o >>= 1) ps += __shfl_xor_sync(0xffffffffu, ps, o);
            l1 = l1 * alpha + ps; m1 = nm;
            #pragma unroll
            for (int j = 0; j < 8; j++) o1[j] *= alpha;
        }
        __syncthreads();
        #pragma unroll 4
        for (int kk = 0; kk < 32; kk++) {
            float p0 = Ps[r0][kk], p1 = Ps[r1][kk];
            #pragma unroll
            for (int j = 0; j < 8; j++) {
                float vv = Vs[kk][d0 + j];
                o0[j] = fmaf(p0, vv, o0[j]);
                o1[j] = fmaf(p1, vv, o1[j]);
            }
        }
        __syncthreads();
    }

    float il0 = 1.0f / l0, il1 = 1.0f / l1;
    size_t base0 = (size_t)(b * S_ + q0 + r0) * (H_ * HD_) + h * HD_ + d0;
    size_t base1 = (size_t)(b * S_ + q0 + r1) * (H_ * HD_) + h * HD_ + d0;
    #pragma unroll
    for (int j = 0; j < 8; j++) {
        out[base0 + j] = tfr(o0[j] * il0);   // pre-round for o-proj GEMM
        out[base1 + j] = tfr(o1[j] * il1);
    }
}

// ---------------- SwiGLU elementwise: gate = tf32(silu(gate) * up) ----------------
__global__ void silu_mul_kernel(float* __restrict__ gate,
                                const float* __restrict__ up, int n) {
    int i = blockIdx.x * blockDim.x + threadIdx.x;
    if (i < n) {
        float g = gate[i];
        float s = g / (1.0f + expf(-g));
        gate[i] = tfr(s * up[i]);           // pre-round for down GEMM
    }
}

// ---------------- host orchestration ----------------
extern "C" void kernel_launch(void* const* d_in, const int* in_sizes, int n_in,
                              void* d_out, int out_size) {
    const float* x      = (const float*)d_in[0];
    const float* wq     = (const float*)d_in[1];
    const float* wk     = (const float*)d_in[2];
    const float* wv     = (const float*)d_in[3];
    const float* wo     = (const float*)d_in[4];
    const float* qnw    = (const float*)d_in[5];
    const float* knw    = (const float*)d_in[6];
    const float* ln1    = (const float*)d_in[7];
    const float* ln2    = (const float*)d_in[8];
    const float* wg     = (const float*)d_in[9];
    const float* wu     = (const float*)d_in[10];
    const float* wd     = (const float*)d_in[11];
    const float* normw  = (const float*)d_in[12];
    const int*   amask  = (const int*)d_in[13];

    float *h, *n, *q, *k, *v, *att, *gate, *up;
    float *cwq, *cwk, *cwv, *cwo, *cwg, *cwu, *cwd;
    cudaGetSymbolAddress((void**)&h,    g_h);
    cudaGetSymbolAddress((void**)&n,    g_n);
    cudaGetSymbolAddress((void**)&q,    g_q);
    cudaGetSymbolAddress((void**)&k,    g_k);
    cudaGetSymbolAddress((void**)&v,    g_v);
    cudaGetSymbolAddress((void**)&att,  g_att);
    cudaGetSymbolAddress((void**)&gate, g_gate);
    cudaGetSymbolAddress((void**)&up,   g_up);
    cudaGetSymbolAddress((void**)&cwq,  g_wq);
    cudaGetSymbolAddress((void**)&cwk,  g_wk);
    cudaGetSymbolAddress((void**)&cwv,  g_wv);
    cudaGetSymbolAddress((void**)&cwo,  g_wo);
    cudaGetSymbolAddress((void**)&cwg,  g_wg);
    cudaGetSymbolAddress((void**)&cwu,  g_wu);
    cudaGetSymbolAddress((void**)&cwd,  g_wd);

    // pre-round all weights to tf32 (RNA) once per call
    {
        struct { const float* s; float* d; int n; } cv[7] = {
            { wq, cwq, L_ * D_ * H_ * HD_ },
            { wk, cwk, L_ * D_ * HK_ * HD_ },
            { wv, cwv, L_ * D_ * HK_ * HD_ },
            { wo, cwo, L_ * H_ * HD_ * D_ },
            { wg, cwg, L_ * D_ * FF_ },
            { wu, cwu, L_ * D_ * FF_ },
            { wd, cwd, L_ * FF_ * D_ },
        };
        for (int i = 0; i < 7; i++) {
            int n4 = cv[i].n / 4;
            tf32_round_kernel<<<(n4 + 255) / 256, 256>>>(cv[i].s, cv[i].d, n4);
        }
    }

    cudaMemcpyAsync(h, x, (size_t)TOK_ * D_ * sizeof(float),
                    cudaMemcpyDeviceToDevice, 0);

    dim3 gQKV (16, TOK_ / 128);              // 512 blocks
    dim3 gGU  (48, TOK_ / 128);              // 1536 blocks
    dim3 g1024(D_ / 128, TOK_ / 128);        // 256 blocks

    for (int l = 0; l < L_; l++) {
        const float* wq_l = cwq + (size_t)l * D_ * H_ * HD_;
        const float* wk_l = cwk + (size_t)l * D_ * HK_ * HD_;
        const float* wv_l = cwv + (size_t)l * D_ * HK_ * HD_;
        const float* wo_l = cwo + (size_t)l * H_ * HD_ * D_;
        const float* wg_l = cwg + (size_t)l * D_ * FF_;
        const float* wu_l = cwu + (size_t)l * D_ * FF_;
        const float* wd_l = cwd + (size_t)l * FF_ * D_;

        rmsnorm_kernel<<<TOK_, 256>>>(h, ln1 + l * D_, n, 1);

        gemm_qkv<<<gQKV, 256>>>(n, wq_l, wk_l, wv_l, q, k, v);

        qknorm_rope_kernel<<<(TOK_ * H_)  / 4, 128>>>(q, qnw + l * HD_, H_);
        qknorm_rope_kernel<<<(TOK_ * HK_) / 4, 128>>>(k, knw + l * HD_, HK_);

        attn_kernel<<<dim3(S_ / 64, H_, B_), 256>>>(
            q, k, v, amask, att, (l & 1) ? WIN_ : -1);

        gemm_tf32<true><<<g1024, 256>>>(att, wo_l, h, D_, H_ * HD_);

        rmsnorm_kernel<<<TOK_, 256>>>(h, ln2 + l * D_, n, 1);

        gemm_gateup<<<gGU, 256>>>(n, wg_l, wu_l, gate, up);

        int nel = TOK_ * FF_;
        silu_mul_kernel<<<(nel + 255) / 256, 256>>>(gate, up, nel);

        gemm_tf32<true><<<g1024, 256>>>(gate, wd_l, h, D_, FF_);
    }

    rmsnorm_kernel<<<TOK_, 256>>>(h, normw, (float*)d_out, 0);
}

// round 7
// speedup vs baseline: 1.6058x; 1.4463x over previous
#include <cuda_runtime.h>
#include <math.h>
#include <float.h>

#define D_    1024
#define H_    16
#define HK_   8
#define HD_   64
#define FF_   3072
#define S_    1024
#define B_    4
#define TOK_  4096   // B*S
#define L_    4
#define WIN_  12

// ---------------- scratch (no allocations allowed) ----------------
__device__ float g_h   [TOK_ * D_];
__device__ float g_n   [TOK_ * D_];
__device__ float g_q   [TOK_ * H_  * HD_];
__device__ float g_k   [TOK_ * HK_ * HD_];
__device__ float g_v   [TOK_ * HK_ * HD_];
__device__ float g_att [TOK_ * H_  * HD_];
__device__ float g_gate[TOK_ * FF_];
__device__ float g_up  [TOK_ * FF_];

// ---------------- helpers ----------------
__device__ __forceinline__ unsigned f2tf(float x) {
    unsigned r;
    asm("cvt.rna.tf32.f32 %0, %1;" : "=r"(r) : "f"(x));
    return r;
}
__device__ __forceinline__ float tfr(float x) { return __uint_as_float(f2tf(x)); }
__device__ __forceinline__ void cpasync16(float* dst_smem, const float* src_gmem) {
    unsigned d = (unsigned)__cvta_generic_to_shared(dst_smem);
    asm volatile("cp.async.cg.shared.global [%0], [%1], 16;"
                 :: "r"(d), "l"(src_gmem));
}
#define CP_COMMIT() asm volatile("cp.async.commit_group;")
#define CP_WAIT0()  asm volatile("cp.async.wait_group 0;")

#define MMA_TF32(acc, a, b)                                              \
    asm volatile(                                                        \
        "mma.sync.aligned.m16n8k8.row.col.f32.tf32.tf32.f32 "            \
        "{%0,%1,%2,%3}, {%4,%5,%6,%7}, {%8,%9}, {%0,%1,%2,%3};"          \
        : "+f"((acc)[0]), "+f"((acc)[1]), "+f"((acc)[2]), "+f"((acc)[3]) \
        : "r"((a)[0]), "r"((a)[1]), "r"((a)[2]), "r"((a)[3]),            \
          "r"((b)[0]), "r"((b)[1]))

// ---------------- rmsnorm over 1024 cols, 1 block per row ----------------
__global__ void rmsnorm_kernel(const float* __restrict__ x,
                               const float* __restrict__ w,
                               float* __restrict__ out) {
    int row = blockIdx.x;
    const float* xr = x + (size_t)row * D_;
    int t = threadIdx.x;               // 256 threads, 4 floats each
    float4 v = *(const float4*)(xr + t * 4);
    float ss = v.x * v.x + v.y * v.y + v.z * v.z + v.w * v.w;
    #pragma unroll
    for (int o = 16; o; o >>= 1) ss += __shfl_xor_sync(0xffffffffu, ss, o);
    __shared__ float sh[8];
    if ((t & 31) == 0) sh[t >> 5] = ss;
    __syncthreads();
    float tot = 0.f;
    #pragma unroll
    for (int i = 0; i < 8; i++) tot += sh[i];
    float scale = rsqrtf(tot * (1.0f / D_) + 1e-6f);
    float4 wv = *(const float4*)(w + t * 4);
    float4 o4;
    o4.x = v.x * scale * wv.x;
    o4.y = v.y * scale * wv.y;
    o4.z = v.z * scale * wv.z;
    o4.w = v.w * scale * wv.w;
    *(float4*)(out + (size_t)row * D_ + t * 4) = o4;
}

// ---------------- TF32 tensor-core GEMM core (cp.async, 8 warps, R4 config) ----------------
#define AST_ 20
#define BST_ 136
template <bool ACC>
__device__ __forceinline__ void gemm_core(const float* __restrict__ A,
                                          const float* __restrict__ B,
                                          float* __restrict__ C,
                                          int N, int K, int bx, int by) {
    __shared__ float As[2][128 * AST_];
    __shared__ float Bs[2][16 * BST_];

    int tid = threadIdx.x;
    int lane = tid & 31, wid = tid >> 5;
    int wr = wid >> 2;          // 0..1  (64-row slab)
    int wc = wid & 3;           // 0..3  (32-col slab)
    int tg = lane & 3;          // k index within fragment
    int grp = lane >> 2;        // m/n index within fragment

    const float* Ag = A + (size_t)(by * 128) * K;
    const float* Bg = B + bx * 128;

    int c0 = tid * 2, c1 = tid * 2 + 1;
    int ar0 = c0 >> 2, ac0 = (c0 & 3) << 2;
    int ar1 = c1 >> 2, ac1 = (c1 & 3) << 2;
    int br0 = c0 >> 5, bc0 = (c0 & 31) << 2;
    int br1 = c1 >> 5, bc1 = (c1 & 31) << 2;

    float acc[4][4][4];
    #pragma unroll
    for (int i = 0; i < 4; i++)
        #pragma unroll
        for (int j = 0; j < 4; j++)
            #pragma unroll
            for (int c = 0; c < 4; c++) acc[i][j][c] = 0.f;

    cpasync16(&As[0][ar0 * AST_ + ac0], Ag + (size_t)ar0 * K + ac0);
    cpasync16(&As[0][ar1 * AST_ + ac1], Ag + (size_t)ar1 * K + ac1);
    cpasync16(&Bs[0][br0 * BST_ + bc0], Bg + (size_t)br0 * N + bc0);
    cpasync16(&Bs[0][br1 * BST_ + bc1], Bg + (size_t)br1 * N + bc1);
    CP_COMMIT();

    int nIter = K >> 4;
    for (int it = 0; it < nIter; it++) {
        int cur = it & 1;
        CP_WAIT0();
        __syncthreads();
        if (it + 1 < nIter) {
            int nxt = cur ^ 1;
            int k0n = (it + 1) << 4;
            cpasync16(&As[nxt][ar0 * AST_ + ac0], Ag + (size_t)ar0 * K + k0n + ac0);
            cpasync16(&As[nxt][ar1 * AST_ + ac1], Ag + (size_t)ar1 * K + k0n + ac1);
            cpasync16(&Bs[nxt][br0 * BST_ + bc0], Bg + (size_t)(k0n + br0) * N + bc0);
            cpasync16(&Bs[nxt][br1 * BST_ + bc1], Bg + (size_t)(k0n + br1) * N + bc1);
            CP_COMMIT();
        }

        #pragma unroll
        for (int kk = 0; kk < 16; kk += 8) {
            unsigned afr[4][4], bfr[4][2];
            #pragma unroll
            for (int mt = 0; mt < 4; mt++) {
                int m = wr * 64 + mt * 16 + grp;
                afr[mt][0] = f2tf(As[cur][m * AST_ + kk + tg]);
                afr[mt][1] = f2tf(As[cur][(m + 8) * AST_ + kk + tg]);
                afr[mt][2] = f2tf(As[cur][m * AST_ + kk + tg + 4]);
                afr[mt][3] = f2tf(As[cur][(m + 8) * AST_ + kk + tg + 4]);
            }
            #pragma unroll
            for (int nt = 0; nt < 4; nt++) {
                int n = wc * 32 + nt * 8 + grp;
                bfr[nt][0] = f2tf(Bs[cur][(kk + tg) * BST_ + n]);
                bfr[nt][1] = f2tf(Bs[cur][(kk + tg + 4) * BST_ + n]);
            }
            #pragma unroll
            for (int mt = 0; mt < 4; mt++)
                #pragma unroll
                for (int nt = 0; nt < 4; nt++)
                    MMA_TF32(acc[mt][nt], afr[mt], bfr[nt]);
        }
        __syncthreads();
    }

    #pragma unroll
    for (int mt = 0; mt < 4; mt++) {
        int row0 = by * 128 + wr * 64 + mt * 16 + grp;
        #pragma unroll
        for (int nt = 0; nt < 4; nt++) {
            int col = bx * 128 + wc * 32 + nt * 8 + tg * 2;
            float* p0 = C + (size_t)row0 * N + col;
            float* p1 = C + (size_t)(row0 + 8) * N + col;
            if (ACC) {
                float2 cc0 = *(float2*)p0, cc1 = *(float2*)p1;
                cc0.x += acc[mt][nt][0]; cc0.y += acc[mt][nt][1];
                cc1.x += acc[mt][nt][2]; cc1.y += acc[mt][nt][3];
                *(float2*)p0 = cc0; *(float2*)p1 = cc1;
            } else {
                *(float2*)p0 = make_float2(acc[mt][nt][0], acc[mt][nt][1]);
                *(float2*)p1 = make_float2(acc[mt][nt][2], acc[mt][nt][3]);
            }
        }
    }
}

template <bool ACC>
__global__ void __launch_bounds__(256, 2)
gemm_tf32(const float* __restrict__ A, const float* __restrict__ B,
          float* __restrict__ C, int N, int K) {
    gemm_core<ACC>(A, B, C, N, K, blockIdx.x, blockIdx.y);
}

__global__ void __launch_bounds__(256, 2)
gemm_qkv(const float* __restrict__ A,
         const float* __restrict__ Wq, const float* __restrict__ Wk,
         const float* __restrict__ Wv,
         float* __restrict__ q, float* __restrict__ k, float* __restrict__ v) {
    int bx = blockIdx.x;
    if (bx < 8)       gemm_core<false>(A, Wq, q, 1024, D_, bx,      blockIdx.y);
    else if (bx < 12) gemm_core<false>(A, Wk, k,  512, D_, bx - 8,  blockIdx.y);
    else              gemm_core<false>(A, Wv, v,  512, D_, bx - 12, blockIdx.y);
}

__global__ void __launch_bounds__(256, 2)
gemm_gateup(const float* __restrict__ A,
            const float* __restrict__ Wg, const float* __restrict__ Wu,
            float* __restrict__ gate, float* __restrict__ up) {
    int bx = blockIdx.x;
    if (bx < 24) gemm_core<false>(A, Wg, gate, FF_, D_, bx,      blockIdx.y);
    else         gemm_core<false>(A, Wu, up,   FF_, D_, bx - 24, blockIdx.y);
}

// ---------------- per-head rmsnorm + RoPE (one warp per (token, head)) ----------------
#define LOG2_THETA 19.9315685693241741f
__global__ void qknorm_rope_kernel(float* __restrict__ x,
                                   const float* __restrict__ w, int nh) {
    int warp = (blockIdx.x * blockDim.x + threadIdx.x) >> 5;
    int lane = threadIdx.x & 31;
    int token = warp / nh;
    int s = token & (S_ - 1);
    float* p = x + (size_t)warp * HD_;
    float a = p[lane], b = p[lane + 32];
    float ss = a * a + b * b;
    #pragma unroll
    for (int o = 16; o; o >>= 1) ss += __shfl_xor_sync(0xffffffffu, ss, o);
    float scale = rsqrtf(ss * (1.0f / HD_) + 1e-6f);
    a *= scale * w[lane];
    b *= scale * w[lane + 32];
    float inv = exp2f(-(float)lane * (LOG2_THETA / 32.0f));
    float ang = (float)s * inv;
    float c = cosf(ang), sn = sinf(ang);
    p[lane]      = a * c - b * sn;
    p[lane + 32] = b * c + a * sn;
}

// ---------------- tensor-core flash attention ----------------
// Block: (b, h, 64 q rows). 128 threads = 4 warps, each warp 16 q rows.
// K-tile 32. QK^T and P*V via mma.sync.tf32; online softmax in fp32.
#define QST 68   // Qs[64][68]  qrow x d      ([m][k], conflict-free frags)
#define KST 68   // Ks[32][68]  key  x d      ([n][k])
#define VST 72   // Vs[32][72]  key  x d      ([k][n])
#define PST 36   // Ps[64][36]  qrow x key    ([m][k])
__global__ void __launch_bounds__(128)
attn_mma_kernel(const float* __restrict__ q, const float* __restrict__ k,
                const float* __restrict__ v, const int* __restrict__ amask,
                float* __restrict__ out, int win) {
    __shared__ float Qs[64 * QST];
    __shared__ float Ks[32 * KST];
    __shared__ float Vs[32 * VST];
    __shared__ float Ps[64 * PST];
    __shared__ float Mk[32];

    int b = blockIdx.z, h = blockIdx.y;
    int q0 = blockIdx.x * 64;
    int kh = h >> 1;
    int tid = threadIdx.x;
    int lane = tid & 31, wid = tid >> 5;
    int tg = lane & 3, grp = lane >> 2;
    int m0 = wid * 16;                 // warp's q-row offset in tile
    int qpos0 = q0 + m0 + grp;         // global q positions for this thread
    int qpos1 = qpos0 + 8;

    // load Q tile (tf32-rounded)
    for (int i = tid; i < 64 * 16; i += 128) {
        int r = i >> 4, c4 = (i & 15) << 2;
        float4 f = *(const float4*)(q + (size_t)(b * S_ + q0 + r) * (H_ * HD_) + h * HD_ + c4);
        Qs[r * QST + c4 + 0] = tfr(f.x);
        Qs[r * QST + c4 + 1] = tfr(f.y);
        Qs[r * QST + c4 + 2] = tfr(f.z);
        Qs[r * QST + c4 + 3] = tfr(f.w);
    }

    float oacc[8][4];
    #pragma unroll
    for (int i = 0; i < 8; i++)
        #pragma unroll
        for (int j = 0; j < 4; j++) oacc[i][j] = 0.f;
    float mr0 = -1e30f, mr1 = -1e30f, l0 = 0.f, l1 = 0.f;

    int kt_lo = 0, kt_hi = (S_ / 32) - 1;
    if (win >= 0) {
        int lo = q0 - win; if (lo < 0) lo = 0;
        int hi = q0 + 63 + win; if (hi > S_ - 1) hi = S_ - 1;
        kt_lo = lo >> 5; kt_hi = hi >> 5;
    }
    const float scale = 0.125f;

    for (int kt = kt_lo; kt <= kt_hi; kt++) {
        // load K,V tiles (tf32-rounded); V in [k][n] layout for B frags
        for (int i = tid; i < 32 * 16; i += 128) {
            int r = i >> 4, c4 = (i & 15) << 2;
            size_t off = (size_t)(b * S_ + kt * 32 + r) * (HK_ * HD_) + kh * HD_ + c4;
            float4 fk = *(const float4*)(k + off);
            float4 fv = *(const float4*)(v + off);
            Ks[r * KST + c4 + 0] = tfr(fk.x);
            Ks[r * KST + c4 + 1] = tfr(fk.y);
            Ks[r * KST + c4 + 2] = tfr(fk.z);
            Ks[r * KST + c4 + 3] = tfr(fk.w);
            Vs[r * VST + c4 + 0] = tfr(fv.x);
            Vs[r * VST + c4 + 1] = tfr(fv.y);
            Vs[r * VST + c4 + 2] = tfr(fv.z);
            Vs[r * VST + c4 + 3] = tfr(fv.w);
        }
        if (tid < 32)
            Mk[tid] = (amask[b * S_ + kt * 32 + tid] != 0) ? 0.f : -1e30f;
        __syncthreads();

        // ---- QK^T: warp rows m0..m0+15 x keys 0..31 ----
        float sc[4][4];
        #pragma unroll
        for (int i = 0; i < 4; i++)
            #pragma unroll
            for (int j = 0; j < 4; j++) sc[i][j] = 0.f;
        #pragma unroll
        for (int k8 = 0; k8 < 64; k8 += 8) {
            unsigned a[4];
            a[0] = __float_as_uint(Qs[(m0 + grp) * QST + k8 + tg]);
            a[1] = __float_as_uint(Qs[(m0 + grp + 8) * QST + k8 + tg]);
            a[2] = __float_as_uint(Qs[(m0 + grp) * QST + k8 + tg + 4]);
            a[3] = __float_as_uint(Qs[(m0 + grp + 8) * QST + k8 + tg + 4]);
            #pragma unroll
            for (int nt = 0; nt < 4; nt++) {
                unsigned bb[2];
                bb[0] = __float_as_uint(Ks[(nt * 8 + grp) * KST + k8 + tg]);
                bb[1] = __float_as_uint(Ks[(nt * 8 + grp) * KST + k8 + tg + 4]);
                MMA_TF32(sc[nt], a, bb);
            }
        }

        // ---- mask + online softmax ----
        float v0[8], v1[8];
        #pragma unroll
        for (int nt = 0; nt < 4; nt++) {
            int kc0 = nt * 8 + 2 * tg, kc1 = kc0 + 1;
            int kp0 = kt * 32 + kc0, kp1 = kt * 32 + kc1;
            float mk0 = Mk[kc0], mk1 = Mk[kc1];
            float a0 = sc[nt][0] * scale + mk0;
            float a1 = sc[nt][1] * scale + mk1;
            float b0 = sc[nt][2] * scale + mk0;
            float b1 = sc[nt][3] * scale + mk1;
            if (win >= 0) {
                if (abs(qpos0 - kp0) > win) a0 = -1e30f;
                if (abs(qpos0 - kp1) > win) a1 = -1e30f;
                if (abs(qpos1 - kp0) > win) b0 = -1e30f;
                if (abs(qpos1 - kp1) > win) b1 = -1e30f;
            }
            v0[nt * 2] = a0; v0[nt * 2 + 1] = a1;
            v1[nt * 2] = b0; v1[nt * 2 + 1] = b1;
        }
        float tm0 = -1e30f, tm1 = -1e30f;
        #pragma unroll
        for (int j = 0; j < 8; j++) { tm0 = fmaxf(tm0, v0[j]); tm1 = fmaxf(tm1, v1[j]); }
        tm0 = fmaxf(tm0, __shfl_xor_sync(0xffffffffu, tm0, 1));
        tm0 = fmaxf(tm0, __shfl_xor_sync(0xffffffffu, tm0, 2));
        tm1 = fmaxf(tm1, __shfl_xor_sync(0xffffffffu, tm1, 1));
        tm1 = fmaxf(tm1, __shfl_xor_sync(0xffffffffu, tm1, 2));
        float nm0 = fmaxf(mr0, tm0), nm1 = fmaxf(mr1, tm1);
        float al0 = __expf(mr0 - nm0), al1 = __expf(mr1 - nm1);
        mr0 = nm0; mr1 = nm1;
        float ps0 = 0.f, ps1 = 0.f;
        #pragma unroll
        for (int nt = 0; nt < 4; nt++) {
            float p00 = __expf(v0[nt * 2]     - nm0);
            float p01 = __expf(v0[nt * 2 + 1] - nm0);
            float p10 = __expf(v1[nt * 2]     - nm1);
            float p11 = __expf(v1[nt * 2 + 1] - nm1);
            ps0 += p00 + p01; ps1 += p10 + p11;
            int col = nt * 8 + 2 * tg;
            *(float2*)&Ps[(m0 + grp) * PST + col]     = make_float2(tfr(p00), tfr(p01));
            *(float2*)&Ps[(m0 + grp + 8) * PST + col] = make_float2(tfr(p10), tfr(p11));
        }
        ps0 += __shfl_xor_sync(0xffffffffu, ps0, 1);
        ps0 += __shfl_xor_sync(0xffffffffu, ps0, 2);
        ps1 += __shfl_xor_sync(0xffffffffu, ps1, 1);
        ps1 += __shfl_xor_sync(0xffffffffu, ps1, 2);
        l0 = l0 * al0 + ps0;
        l1 = l1 * al1 + ps1;
        #pragma unroll
        for (int nt = 0; nt < 8; nt++) {
            oacc[nt][0] *= al0; oacc[nt][1] *= al0;
            oacc[nt][2] *= al1; oacc[nt][3] *= al1;
        }
        __syncwarp();

        // ---- P @ V : rows m0..m0+15 x d 0..63, k = keys 0..31 ----
        #pragma unroll
        for (int k8 = 0; k8 < 32; k8 += 8) {
            unsigned a[4];
            a[0] = __float_as_uint(Ps[(m0 + grp) * PST + k8 + tg]);
            a[1] = __float_as_uint(Ps[(m0 + grp + 8) * PST + k8 + tg]);
            a[2] = __float_as_uint(Ps[(m0 + grp) * PST + k8 + tg + 4]);
            a[3] = __float_as_uint(Ps[(m0 + grp + 8) * PST + k8 + tg + 4]);
            #pragma unroll
            for (int nt = 0; nt < 8; nt++) {
                unsigned bb[2];
                bb[0] = __float_as_uint(Vs[(k8 + tg) * VST + nt * 8 + grp]);
                bb[1] = __float_as_uint(Vs[(k8 + tg + 4) * VST + nt * 8 + grp]);
                MMA_TF32(oacc[nt], a, bb);
            }
        }
        __syncthreads();
    }

    float il0 = 1.0f / l0, il1 = 1.0f / l1;
    size_t base0 = (size_t)(b * S_ + qpos0 - b * 0) * 0; // (unused, kept simple below)
    (void)base0;
    #pragma unroll
    for (int nt = 0; nt < 8; nt++) {
        int col = h * HD_ + nt * 8 + 2 * tg;
        float* p0 = out + (size_t)(b * S_ + qpos0) * (H_ * HD_) + col;
        float* p1 = out + (size_t)(b * S_ + qpos1) * (H_ * HD_) + col;
        *(float2*)p0 = make_float2(oacc[nt][0] * il0, oacc[nt][1] * il0);
        *(float2*)p1 = make_float2(oacc[nt][2] * il1, oacc[nt][3] * il1);
    }
}

// ---------------- SwiGLU elementwise: gate = silu(gate) * up ----------------
__global__ void silu_mul_kernel(float* __restrict__ gate,
                                const float* __restrict__ up, int n) {
    int i = blockIdx.x * blockDim.x + threadIdx.x;
    if (i < n) {
        float g = gate[i];
        float s = g / (1.0f + __expf(-g));
        gate[i] = s * up[i];
    }
}

// ---------------- host orchestration ----------------
extern "C" void kernel_launch(void* const* d_in, const int* in_sizes, int n_in,
                              void* d_out, int out_size) {
    const float* x      = (const float*)d_in[0];
    const float* wq     = (const float*)d_in[1];
    const float* wk     = (const float*)d_in[2];
    const float* wv     = (const float*)d_in[3];
    const float* wo     = (const float*)d_in[4];
    const float* qnw    = (const float*)d_in[5];
    const float* knw    = (const float*)d_in[6];
    const float* ln1    = (const float*)d_in[7];
    const float* ln2    = (const float*)d_in[8];
    const float* wg     = (const float*)d_in[9];
    const float* wu     = (const float*)d_in[10];
    const float* wd     = (const float*)d_in[11];
    const float* normw  = (const float*)d_in[12];
    const int*   amask  = (const int*)d_in[13];

    float *h, *n, *q, *k, *v, *att, *gate, *up;
    cudaGetSymbolAddress((void**)&h,    g_h);
    cudaGetSymbolAddress((void**)&n,    g_n);
    cudaGetSymbolAddress((void**)&q,    g_q);
    cudaGetSymbolAddress((void**)&k,    g_k);
    cudaGetSymbolAddress((void**)&v,    g_v);
    cudaGetSymbolAddress((void**)&att,  g_att);
    cudaGetSymbolAddress((void**)&gate, g_gate);
    cudaGetSymbolAddress((void**)&up,   g_up);

    cudaMemcpyAsync(h, x, (size_t)TOK_ * D_ * sizeof(float),
                    cudaMemcpyDeviceToDevice, 0);

    dim3 gQKV (16, TOK_ / 128);              // 512 blocks
    dim3 gGU  (48, TOK_ / 128);              // 1536 blocks
    dim3 g1024(D_ / 128, TOK_ / 128);        // 256 blocks

    for (int l = 0; l < L_; l++) {
        const float* wq_l = wq + (size_t)l * D_ * H_ * HD_;
        const float* wk_l = wk + (size_t)l * D_ * HK_ * HD_;
        const float* wv_l = wv + (size_t)l * D_ * HK_ * HD_;
        const float* wo_l = wo + (size_t)l * H_ * HD_ * D_;
        const float* wg_l = wg + (size_t)l * D_ * FF_;
        const float* wu_l = wu + (size_t)l * D_ * FF_;
        const float* wd_l = wd + (size_t)l * FF_ * D_;

        rmsnorm_kernel<<<TOK_, 256>>>(h, ln1 + l * D_, n);

        gemm_qkv<<<gQKV, 256>>>(n, wq_l, wk_l, wv_l, q, k, v);

        qknorm_rope_kernel<<<(TOK_ * H_)  / 4, 128>>>(q, qnw + l * HD_, H_);
        qknorm_rope_kernel<<<(TOK_ * HK_) / 4, 128>>>(k, knw + l * HD_, HK_);

        attn_mma_kernel<<<dim3(S_ / 64, H_, B_), 128>>>(
            q, k, v, amask, att, (l & 1) ? WIN_ : -1);

        gemm_tf32<true><<<g1024, 256>>>(att, wo_l, h, D_, H_ * HD_);

        rmsnorm_kernel<<<TOK_, 256>>>(h, ln2 + l * D_, n);

        gemm_gateup<<<gGU, 256>>>(n, wg_l, wu_l, gate, up);

        int nel = TOK_ * FF_;
        silu_mul_kernel<<<(nel + 255) / 256, 256>>>(gate, up, nel);

        gemm_tf32<true><<<g1024, 256>>>(gate, wd_l, h, D_, FF_);
    }

    rmsnorm_kernel<<<TOK_, 256>>>(h, normw, (float*)d_out);
}